// round 1
// baseline (speedup 1.0000x reference)
#include <cuda_runtime.h>
#include <cstdint>

#define NB 2
#define NN 50000
#define NF 128
#define NE 500000

// ---------------- scratch (device globals; no allocation allowed) ----------------
__device__ int   g_cnt[NN];
__device__ int   g_off[NN + 1];
__device__ int   g_cur[NN];
__device__ int   g_elist[NE];
__device__ float g_w0T[2 * NF * NF];   // [256][128]  (k-major, o contiguous)
__device__ float g_w1T[NF * NF];       // [128][128]

// ---------------- kernel 1: zero counts + transpose weights ----------------
__global__ void k_prep(const float* __restrict__ w0, const float* __restrict__ w1) {
    int i = blockIdx.x * blockDim.x + threadIdx.x;
    if (i < NN) g_cnt[i] = 0;
    if (i < 2 * NF * NF) {           // w0: [o=128][k=256] -> w0T[k][o]
        int o = i / (2 * NF);
        int k = i % (2 * NF);
        g_w0T[k * NF + o] = w0[i];
    }
    if (i < NF * NF) {               // w1: [o=128][k=128] -> w1T[k][o]
        int o = i / NF;
        int k = i % NF;
        g_w1T[k * NF + o] = w1[i];
    }
}

// ---------------- kernel 2: degree histogram ----------------
__global__ void k_hist(const int* __restrict__ dst) {
    int e = blockIdx.x * blockDim.x + threadIdx.x;
    if (e < NE) atomicAdd(&g_cnt[dst[e]], 1);
}

// ---------------- kernel 3: exclusive scan (single block) ----------------
__global__ void k_scan() {
    __shared__ int part[1024];
    int t = threadIdx.x;
    const int CH = (NN + 1023) / 1024;
    int lo = t * CH;
    int hi = lo + CH; if (hi > NN) hi = NN;
    int s = 0;
    for (int i = lo; i < hi; i++) s += g_cnt[i];
    part[t] = s;
    __syncthreads();
    for (int d = 1; d < 1024; d <<= 1) {
        int v = (t >= d) ? part[t - d] : 0;
        __syncthreads();
        part[t] += v;
        __syncthreads();
    }
    int run = (t == 0) ? 0 : part[t - 1];
    for (int i = lo; i < hi; i++) {
        g_off[i] = run;
        g_cur[i] = run;
        run += g_cnt[i];
    }
    if (t == 1023) g_off[NN] = part[1023];
}

// ---------------- kernel 4: CSR fill ----------------
__global__ void k_fill(const int* __restrict__ dst, const int* __restrict__ src) {
    int e = blockIdx.x * blockDim.x + threadIdx.x;
    if (e < NE) {
        int d = dst[e];
        int p = atomicAdd(&g_cur[d], 1);
        g_elist[p] = src[e];
    }
}

// ---------------- kernel 5: fused reduce + MLP ----------------
// 512 threads, tile = 32 nodes = 64 rows (row = node*2 + b).
// smem: xs[64][256] | hs[64][128] | w1s[128][128] | w0s[128][128] (chunk) = 224 KB
#define SM_XS  0
#define SM_HS  16384
#define SM_W1  24576
#define SM_W0  40960
#define SM_FLOATS 57344

__global__ __launch_bounds__(512, 1)
void k_main(const float* __restrict__ x0, const float* __restrict__ b0,
            const float* __restrict__ b1, float* __restrict__ out) {
    extern __shared__ float sm[];
    float* xs  = sm + SM_XS;
    float* hs  = sm + SM_HS;
    float* w1s = sm + SM_W1;
    float* w0s = sm + SM_W0;

    const int t    = threadIdx.x;
    const int warp = t >> 5;
    const int lane = t & 31;
    const int node0 = blockIdx.x * 32;

    // cooperative load of w1T into smem (16384 floats = 4096 float4)
    {
        const float4* s4 = (const float4*)g_w1T;
        float4* d4 = (float4*)w1s;
        for (int i = t; i < 4096; i += 512) d4[i] = s4[i];
    }

    // ---- reduce: each warp handles 2 nodes; lane owns float4 of features ----
    const float NEG_INF = __int_as_float(0xff800000);
    #pragma unroll
    for (int nn = 0; nn < 2; nn++) {
        int ln = warp * 2 + nn;          // local node 0..31
        int n  = node0 + ln;
        float4 s0 = make_float4(0.f, 0.f, 0.f, 0.f), s1 = s0;
        float4 m0 = make_float4(NEG_INF, NEG_INF, NEG_INF, NEG_INF), m1 = m0;
        int deg = 0;
        if (n < NN) {
            int beg = g_off[n], end = g_off[n + 1];
            deg = end - beg;
            for (int ei = beg; ei < end; ei++) {
                int sidx = g_elist[ei];
                float4 v0 = ((const float4*)x0)[sidx * 32 + lane];
                float4 v1 = ((const float4*)x0)[NN * 32 + sidx * 32 + lane];
                s0.x += v0.x; s0.y += v0.y; s0.z += v0.z; s0.w += v0.w;
                s1.x += v1.x; s1.y += v1.y; s1.z += v1.z; s1.w += v1.w;
                m0.x = fmaxf(m0.x, v0.x); m0.y = fmaxf(m0.y, v0.y);
                m0.z = fmaxf(m0.z, v0.z); m0.w = fmaxf(m0.w, v0.w);
                m1.x = fmaxf(m1.x, v1.x); m1.y = fmaxf(m1.y, v1.y);
                m1.z = fmaxf(m1.z, v1.z); m1.w = fmaxf(m1.w, v1.w);
            }
        }
        float* xr0 = xs + (ln * 2 + 0) * 256;
        float* xr1 = xs + (ln * 2 + 1) * 256;
        if (n < NN) {
            float4 mean0, mean1, amax0, amax1;
            if (deg > 0) {
                float inv = 1.0f / (float)deg;
                mean0 = make_float4(s0.x * inv, s0.y * inv, s0.z * inv, s0.w * inv);
                mean1 = make_float4(s1.x * inv, s1.y * inv, s1.z * inv, s1.w * inv);
                amax0 = m0; amax1 = m1;
            } else {
                float4 v0 = ((const float4*)x0)[n * 32 + lane];
                float4 v1 = ((const float4*)x0)[NN * 32 + n * 32 + lane];
                mean0 = v0; amax0 = v0;
                mean1 = v1; amax1 = v1;
            }
            ((float4*)xr0)[lane]              = mean0;
            ((float4*)(xr0 + 128))[lane]      = amax0;
            ((float4*)xr1)[lane]              = mean1;
            ((float4*)(xr1 + 128))[lane]      = amax1;
        } else {
            float4 z = make_float4(0.f, 0.f, 0.f, 0.f);
            ((float4*)xr0)[lane]         = z;
            ((float4*)(xr0 + 128))[lane] = z;
            ((float4*)xr1)[lane]         = z;
            ((float4*)(xr1 + 128))[lane] = z;
        }
    }

    // ---- GEMM1: h = relu(x @ w0T + b0) ----
    // thread -> (o = lane + 32j, j<4; rows = warp*4 + r, r<4)
    float acc[4][4];
    #pragma unroll
    for (int j = 0; j < 4; j++) {
        float bb = b0[lane + 32 * j];
        #pragma unroll
        for (int r = 0; r < 4; r++) acc[j][r] = bb;
    }

    #pragma unroll
    for (int kc = 0; kc < 2; kc++) {
        __syncthreads();
        {
            const float4* s4 = (const float4*)(g_w0T + kc * 16384);
            float4* d4 = (float4*)w0s;
            for (int i = t; i < 4096; i += 512) d4[i] = s4[i];
        }
        __syncthreads();
        const float* xrow = xs + (warp * 4) * 256 + kc * 128;
        #pragma unroll 4
        for (int k = 0; k < 128; k++) {
            float wv[4], xv[4];
            #pragma unroll
            for (int j = 0; j < 4; j++) wv[j] = w0s[k * 128 + lane + 32 * j];
            #pragma unroll
            for (int r = 0; r < 4; r++) xv[r] = xrow[r * 256 + k];
            #pragma unroll
            for (int j = 0; j < 4; j++)
                #pragma unroll
                for (int r = 0; r < 4; r++)
                    acc[j][r] = fmaf(xv[r], wv[j], acc[j][r]);
        }
    }

    // store h tile (relu). Rows warp*4..+3 are produced and consumed by this warp.
    #pragma unroll
    for (int j = 0; j < 4; j++)
        #pragma unroll
        for (int r = 0; r < 4; r++)
            hs[(warp * 4 + r) * 128 + lane + 32 * j] = fmaxf(acc[j][r], 0.f);
    __syncwarp();

    // ---- GEMM2: out = x0 + h @ w1T + b1 ----
    float acc2[4][4];
    #pragma unroll
    for (int j = 0; j < 4; j++) {
        float bb = b1[lane + 32 * j];
        #pragma unroll
        for (int r = 0; r < 4; r++) acc2[j][r] = bb;
    }
    const float* hrow = hs + (warp * 4) * 128;
    #pragma unroll 4
    for (int k = 0; k < 128; k++) {
        float wv[4], hv[4];
        #pragma unroll
        for (int j = 0; j < 4; j++) wv[j] = w1s[k * 128 + lane + 32 * j];
        #pragma unroll
        for (int r = 0; r < 4; r++) hv[r] = hrow[r * 128 + k];
        #pragma unroll
        for (int j = 0; j < 4; j++)
            #pragma unroll
            for (int r = 0; r < 4; r++)
                acc2[j][r] = fmaf(hv[r], wv[j], acc2[j][r]);
    }

    #pragma unroll
    for (int r = 0; r < 4; r++) {
        int row = warp * 4 + r;
        int n = node0 + (row >> 1);
        if (n < NN) {
            int b = row & 1;
            int base = b * NN * NF + n * NF;
            #pragma unroll
            for (int j = 0; j < 4; j++) {
                int o = lane + 32 * j;
                out[base + o] = x0[base + o] + acc2[j][r];
            }
        }
    }
}

// ---------------- launcher ----------------
extern "C" void kernel_launch(void* const* d_in, const int* in_sizes, int n_in,
                              void* d_out, int out_size) {
    const float* x0  = (const float*)d_in[0];
    const int*   dst = (const int*)d_in[1];
    const int*   src = (const int*)d_in[2];
    const float* w0  = (const float*)d_in[3];
    const float* b0  = (const float*)d_in[4];
    const float* w1  = (const float*)d_in[5];
    const float* b1  = (const float*)d_in[6];
    float* out = (float*)d_out;

    static bool attr_set = false;
    // cudaFuncSetAttribute is idempotent and not a captured stream op.
    cudaFuncSetAttribute(k_main, cudaFuncAttributeMaxDynamicSharedMemorySize,
                         SM_FLOATS * (int)sizeof(float));
    (void)attr_set;

    k_prep<<<(NN + 255) / 256, 256>>>(w0, w1);
    k_hist<<<(NE + 255) / 256, 256>>>(dst);
    k_scan<<<1, 1024>>>();
    k_fill<<<(NE + 255) / 256, 256>>>(dst, src);

    int tiles = (NN + 31) / 32;   // 1563
    k_main<<<tiles, 512, SM_FLOATS * (int)sizeof(float)>>>(x0, b0, b1, out);
}

// round 2
// speedup vs baseline: 1.8533x; 1.8533x over previous
#include <cuda_runtime.h>
#include <cstdint>

#define NB 2
#define NN 50000
#define NF 128
#define NE 500000

// ---------------- scratch ----------------
__device__ int g_cnt[NN];
__device__ int g_off[NN + 1];
__device__ int g_cur[NN];
__device__ int g_elist[NE];

// ---------------- kernel 1: zero counts ----------------
__global__ void k_prep() {
    int i = blockIdx.x * blockDim.x + threadIdx.x;
    if (i < NN) g_cnt[i] = 0;
}

// ---------------- kernel 2: degree histogram ----------------
__global__ void k_hist(const int* __restrict__ dst) {
    int e = blockIdx.x * blockDim.x + threadIdx.x;
    if (e < NE) atomicAdd(&g_cnt[dst[e]], 1);
}

// ---------------- kernel 3: exclusive scan (single block) ----------------
__global__ void k_scan() {
    __shared__ int part[1024];
    int t = threadIdx.x;
    const int CH = (NN + 1023) / 1024;
    int lo = t * CH;
    int hi = lo + CH; if (hi > NN) hi = NN;
    int s = 0;
    for (int i = lo; i < hi; i++) s += g_cnt[i];
    part[t] = s;
    __syncthreads();
    for (int d = 1; d < 1024; d <<= 1) {
        int v = (t >= d) ? part[t - d] : 0;
        __syncthreads();
        part[t] += v;
        __syncthreads();
    }
    int run = (t == 0) ? 0 : part[t - 1];
    for (int i = lo; i < hi; i++) {
        g_off[i] = run;
        g_cur[i] = run;
        run += g_cnt[i];
    }
    if (t == 1023) g_off[NN] = part[1023];
}

// ---------------- kernel 4: CSR fill ----------------
__global__ void k_fill(const int* __restrict__ dst, const int* __restrict__ src) {
    int e = blockIdx.x * blockDim.x + threadIdx.x;
    if (e < NE) {
        int d = dst[e];
        int p = atomicAdd(&g_cur[d], 1);
        g_elist[p] = src[e];
    }
}

// ---------------- kernel 5: fused reduce + tf32 tensor-core MLP ----------------
#define ROWS 128           // 64 nodes * B(2)
#define NODES_PER_BLK 64
#define STRA 260           // A row stride (floats): (row*260+k)%32 == (row*4+k)%32 -> conflict-free
#define STRB 132           // B/h row stride
#define XS_FLOATS (ROWS * STRA)     // 33280
#define WB_FLOATS (128 * STRB)      // 16896
#define SM_FLOATS (XS_FLOATS + WB_FLOATS)   // 50176 floats = 200704 B

__device__ __forceinline__ uint32_t f2tf(float f) {
    uint32_t r;
    asm("cvt.rna.tf32.f32 %0, %1;" : "=r"(r) : "f"(f));
    return r;
}
__device__ __forceinline__ float f2tff(float f) { return __uint_as_float(f2tf(f)); }

__device__ __forceinline__ void mma8(float d[4],
                                     uint32_t a0, uint32_t a1, uint32_t a2, uint32_t a3,
                                     uint32_t b0, uint32_t b1) {
    asm volatile(
        "mma.sync.aligned.m16n8k8.row.col.f32.tf32.tf32.f32 "
        "{%0,%1,%2,%3}, {%4,%5,%6,%7}, {%8,%9}, {%0,%1,%2,%3};\n"
        : "+f"(d[0]), "+f"(d[1]), "+f"(d[2]), "+f"(d[3])
        : "r"(a0), "r"(a1), "r"(a2), "r"(a3), "r"(b0), "r"(b1));
}

__global__ __launch_bounds__(512, 1)
void k_main(const float* __restrict__ x0, const float* __restrict__ w0,
            const float* __restrict__ b0v, const float* __restrict__ w1,
            const float* __restrict__ b1v, float* __restrict__ out) {
    extern __shared__ float sm[];
    float* xs = sm;                 // [128][STRA] A tile (tf32 bits)
    float* wb = sm + XS_FLOATS;     // [128][STRB] weight chunk
    float* hs = sm;                 // h tile reuses xs region after GEMM1

    const int t = threadIdx.x;
    const int warp = t >> 5;
    const int lane = t & 31;
    const int gid = lane >> 2;      // 0..7
    const int tig = lane & 3;       // 0..3
    const int node0 = blockIdx.x * NODES_PER_BLK;

    // ======== phase 1: gather + segment mean/max into xs (tf32) ========
    const float NEG_INF = __int_as_float(0xff800000);
    #pragma unroll
    for (int nn = 0; nn < 4; nn++) {
        int ln = warp * 4 + nn;         // local node 0..63
        int n = node0 + ln;
        float4 s0 = make_float4(0.f, 0.f, 0.f, 0.f), s1 = s0;
        float4 m0 = make_float4(NEG_INF, NEG_INF, NEG_INF, NEG_INF), m1 = m0;
        int deg = 0;
        if (n < NN) {
            int beg = g_off[n], end = g_off[n + 1];
            deg = end - beg;
            for (int ei = beg; ei < end; ei++) {
                int sidx = g_elist[ei];
                float4 v0 = ((const float4*)x0)[sidx * 32 + lane];
                float4 v1 = ((const float4*)x0)[NN * 32 + sidx * 32 + lane];
                s0.x += v0.x; s0.y += v0.y; s0.z += v0.z; s0.w += v0.w;
                s1.x += v1.x; s1.y += v1.y; s1.z += v1.z; s1.w += v1.w;
                m0.x = fmaxf(m0.x, v0.x); m0.y = fmaxf(m0.y, v0.y);
                m0.z = fmaxf(m0.z, v0.z); m0.w = fmaxf(m0.w, v0.w);
                m1.x = fmaxf(m1.x, v1.x); m1.y = fmaxf(m1.y, v1.y);
                m1.z = fmaxf(m1.z, v1.z); m1.w = fmaxf(m1.w, v1.w);
            }
        }
        float* r0p = xs + (ln * 2 + 0) * STRA;
        float* r1p = xs + (ln * 2 + 1) * STRA;
        float4 mean0, mean1, amax0, amax1;
        if (n < NN && deg > 0) {
            float inv = 1.0f / (float)deg;
            mean0 = make_float4(s0.x * inv, s0.y * inv, s0.z * inv, s0.w * inv);
            mean1 = make_float4(s1.x * inv, s1.y * inv, s1.z * inv, s1.w * inv);
            amax0 = m0; amax1 = m1;
        } else if (n < NN) {
            float4 v0 = ((const float4*)x0)[n * 32 + lane];
            float4 v1 = ((const float4*)x0)[NN * 32 + n * 32 + lane];
            mean0 = v0; amax0 = v0;
            mean1 = v1; amax1 = v1;
        } else {
            float4 z = make_float4(0.f, 0.f, 0.f, 0.f);
            mean0 = z; mean1 = z; amax0 = z; amax1 = z;
        }
        // tf32-round and store: mean -> cols [0,128), amax -> cols [128,256)
        float4 c;
        c.x = f2tff(mean0.x); c.y = f2tff(mean0.y); c.z = f2tff(mean0.z); c.w = f2tff(mean0.w);
        ((float4*)r0p)[lane] = c;
        c.x = f2tff(amax0.x); c.y = f2tff(amax0.y); c.z = f2tff(amax0.z); c.w = f2tff(amax0.w);
        ((float4*)(r0p + 128))[lane] = c;
        c.x = f2tff(mean1.x); c.y = f2tff(mean1.y); c.z = f2tff(mean1.z); c.w = f2tff(mean1.w);
        ((float4*)r1p)[lane] = c;
        c.x = f2tff(amax1.x); c.y = f2tff(amax1.y); c.z = f2tff(amax1.z); c.w = f2tff(amax1.w);
        ((float4*)(r1p + 128))[lane] = c;
    }

    // ======== warp tile mapping: 32 rows x 32 cols ========
    const int rg = warp >> 2;          // 0..3 -> rows [rg*32, rg*32+32)
    const int cg = warp & 3;           // 0..3 -> cols [cg*32, cg*32+32)
    const int mr = rg * 32;
    const int nc = cg * 32;

    // ======== GEMM1: h = relu(x @ w0^T + b0), K=256 in 2 chunks ========
    float d1[2][4][4];
    #pragma unroll
    for (int j = 0; j < 4; j++) {
        int c0 = nc + 8 * j + 2 * tig;
        float bb0 = b0v[c0], bb1 = b0v[c0 + 1];
        #pragma unroll
        for (int mi = 0; mi < 2; mi++) {
            d1[mi][j][0] = bb0; d1[mi][j][1] = bb1;
            d1[mi][j][2] = bb0; d1[mi][j][3] = bb1;
        }
    }

    const uint32_t* xsu = (const uint32_t*)xs;
    const uint32_t* wbu = (const uint32_t*)wb;

    #pragma unroll
    for (int kc = 0; kc < 2; kc++) {
        __syncthreads();
        // stage w0 chunk [128 out][128 k] -> wb (tf32-rounded)
        for (int i = t; i < 128 * 32; i += 512) {
            int col = i >> 5;
            int q = i & 31;
            float4 v = ((const float4*)(w0 + col * 256 + kc * 128))[q];
            float4 c;
            c.x = f2tff(v.x); c.y = f2tff(v.y); c.z = f2tff(v.z); c.w = f2tff(v.w);
            *(float4*)(wb + col * STRB + q * 4) = c;
        }
        __syncthreads();

        #pragma unroll 4
        for (int ks = 0; ks < 16; ks++) {
            int kk = kc * 128 + ks * 8;
            uint32_t a[2][4], b[4][2];
            #pragma unroll
            for (int mi = 0; mi < 2; mi++) {
                int r0 = mr + mi * 16 + gid;
                a[mi][0] = xsu[r0 * STRA + kk + tig];
                a[mi][1] = xsu[(r0 + 8) * STRA + kk + tig];
                a[mi][2] = xsu[r0 * STRA + kk + tig + 4];
                a[mi][3] = xsu[(r0 + 8) * STRA + kk + tig + 4];
            }
            #pragma unroll
            for (int j = 0; j < 4; j++) {
                int c = nc + 8 * j + gid;
                b[j][0] = wbu[c * STRB + ks * 8 + tig];
                b[j][1] = wbu[c * STRB + ks * 8 + tig + 4];
            }
            #pragma unroll
            for (int mi = 0; mi < 2; mi++)
                #pragma unroll
                for (int j = 0; j < 4; j++)
                    mma8(d1[mi][j], a[mi][0], a[mi][1], a[mi][2], a[mi][3],
                         b[j][0], b[j][1]);
        }
    }

    __syncthreads();   // xs and wb fully consumed

    // store relu(h) as tf32 into hs[row][k] (stride STRB); also stage w1 into wb
    #pragma unroll
    for (int mi = 0; mi < 2; mi++) {
        #pragma unroll
        for (int j = 0; j < 4; j++) {
            int r0 = mr + mi * 16 + gid;
            int c0 = nc + 8 * j + 2 * tig;
            hs[r0 * STRB + c0]           = f2tff(fmaxf(d1[mi][j][0], 0.f));
            hs[r0 * STRB + c0 + 1]       = f2tff(fmaxf(d1[mi][j][1], 0.f));
            hs[(r0 + 8) * STRB + c0]     = f2tff(fmaxf(d1[mi][j][2], 0.f));
            hs[(r0 + 8) * STRB + c0 + 1] = f2tff(fmaxf(d1[mi][j][3], 0.f));
        }
    }
    for (int i = t; i < 128 * 32; i += 512) {
        int col = i >> 5;
        int q = i & 31;
        float4 v = ((const float4*)(w1 + col * 128))[q];
        float4 c;
        c.x = f2tff(v.x); c.y = f2tff(v.y); c.z = f2tff(v.z); c.w = f2tff(v.w);
        *(float4*)(wb + col * STRB + q * 4) = c;
    }
    __syncthreads();

    // ======== GEMM2: out = x0 + h @ w1^T + b1, K=128 ========
    float d2[2][4][4];
    #pragma unroll
    for (int j = 0; j < 4; j++) {
        int c0 = nc + 8 * j + 2 * tig;
        float bb0 = b1v[c0], bb1 = b1v[c0 + 1];
        #pragma unroll
        for (int mi = 0; mi < 2; mi++) {
            d2[mi][j][0] = bb0; d2[mi][j][1] = bb1;
            d2[mi][j][2] = bb0; d2[mi][j][3] = bb1;
        }
    }
    const uint32_t* hsu = (const uint32_t*)hs;

    #pragma unroll 4
    for (int ks = 0; ks < 16; ks++) {
        int kk = ks * 8;
        uint32_t a[2][4], b[4][2];
        #pragma unroll
        for (int mi = 0; mi < 2; mi++) {
            int r0 = mr + mi * 16 + gid;
            a[mi][0] = hsu[r0 * STRB + kk + tig];
            a[mi][1] = hsu[(r0 + 8) * STRB + kk + tig];
            a[mi][2] = hsu[r0 * STRB + kk + tig + 4];
            a[mi][3] = hsu[(r0 + 8) * STRB + kk + tig + 4];
        }
        #pragma unroll
        for (int j = 0; j < 4; j++) {
            int c = nc + 8 * j + gid;
            b[j][0] = wbu[c * STRB + kk + tig];
            b[j][1] = wbu[c * STRB + kk + tig + 4];
        }
        #pragma unroll
        for (int mi = 0; mi < 2; mi++)
            #pragma unroll
            for (int j = 0; j < 4; j++)
                mma8(d2[mi][j], a[mi][0], a[mi][1], a[mi][2], a[mi][3],
                     b[j][0], b[j][1]);
    }

    // ======== epilogue: residual + store ========
    #pragma unroll
    for (int mi = 0; mi < 2; mi++) {
        #pragma unroll
        for (int j = 0; j < 4; j++) {
            int c0 = nc + 8 * j + 2 * tig;
            #pragma unroll
            for (int h = 0; h < 2; h++) {        // h=0: rows r0, h=1: rows r0+8
                int r = mr + mi * 16 + gid + h * 8;
                int n = node0 + (r >> 1);
                if (n < NN) {
                    int b = r & 1;
                    int base = b * NN * NF + n * NF + c0;
                    float2 xv = *(const float2*)(x0 + base);
                    float2 o;
                    o.x = xv.x + d2[mi][j][h * 2 + 0];
                    o.y = xv.y + d2[mi][j][h * 2 + 1];
                    *(float2*)(out + base) = o;
                }
            }
        }
    }
}

// ---------------- launcher ----------------
extern "C" void kernel_launch(void* const* d_in, const int* in_sizes, int n_in,
                              void* d_out, int out_size) {
    const float* x0  = (const float*)d_in[0];
    const int*   dst = (const int*)d_in[1];
    const int*   src = (const int*)d_in[2];
    const float* w0  = (const float*)d_in[3];
    const float* b0  = (const float*)d_in[4];
    const float* w1  = (const float*)d_in[5];
    const float* b1  = (const float*)d_in[6];
    float* out = (float*)d_out;

    cudaFuncSetAttribute(k_main, cudaFuncAttributeMaxDynamicSharedMemorySize,
                         SM_FLOATS * (int)sizeof(float));

    k_prep<<<(NN + 255) / 256, 256>>>();
    k_hist<<<(NE + 255) / 256, 256>>>(dst);
    k_scan<<<1, 1024>>>();
    k_fill<<<(NE + 255) / 256, 256>>>(dst, src);

    int tiles = (NN + NODES_PER_BLK - 1) / NODES_PER_BLK;   // 782
    k_main<<<tiles, 512, SM_FLOATS * (int)sizeof(float)>>>(x0, w0, b0, w1, b1, out);
}